// round 14
// baseline (speedup 1.0000x reference)
#include <cuda_runtime.h>
#include <cuda_fp16.h>
#include <cstdint>

#define NBATCH 4
#define NTOK   4096
#define DIM    512
#define MTOT   (NBATCH * NTOK)
#define SM_SCALE 0.044194173824159216f   // 1/sqrt(512)
#define NCOLBLK (NTOK / 128)             // 32 scores column blocks

// ---------------- scratch (half precision) ----------------
__device__ __half g_Q [(size_t)MTOT * DIM];            // 16 MB, cols perm16, pre-scaled
__device__ __half g_K [(size_t)MTOT * DIM];            // 16 MB, cols perm16
__device__ __half g_Vt[(size_t)MTOT * DIM];            // 16 MB, per-batch [dim][tok], tok perm16
__device__ __half g_S [(size_t)NBATCH * NTOK * NTOK];  // 134 MB (hosts prepped inputs pre-scores)
__device__ __half g_Wt[3ULL * DIM * DIM];              // 1.5 MB transposed + perm16
__device__ float  g_part[(size_t)NBATCH * NCOLBLK * NTOK];  // 2 MB partial row sums of exp(S)

// ---------------- helpers ----------------
__device__ __forceinline__ int pos16(int j) {
    return ((j & 6) << 1) | ((j & 8) >> 2) | (j & 1);
}
__device__ __forceinline__ void mma_f16(float* d, const uint32_t* a, const uint32_t* b) {
    asm volatile(
        "mma.sync.aligned.m16n8k16.row.col.f32.f16.f16.f32 "
        "{%0,%1,%2,%3}, {%4,%5,%6,%7}, {%8,%9}, {%0,%1,%2,%3};"
        : "+f"(d[0]), "+f"(d[1]), "+f"(d[2]), "+f"(d[3])
        : "r"(a[0]), "r"(a[1]), "r"(a[2]), "r"(a[3]), "r"(b[0]), "r"(b[1]));
}
__device__ __forceinline__ uint32_t smem_u32(const void* p) {
    uint32_t r;
    asm("{ .reg .u64 t; cvta.to.shared.u64 t, %1; cvt.u32.u64 %0, t; }" : "=r"(r) : "l"(p));
    return r;
}
__device__ __forceinline__ void cpa16(uint32_t dst, const void* src) {
    asm volatile("cp.async.cg.shared.global [%0], [%1], 16;" :: "r"(dst), "l"(src));
}
#define CP_COMMIT() asm volatile("cp.async.commit_group;" ::: "memory")
#define CP_WAIT2()  asm volatile("cp.async.wait_group 2;" ::: "memory")

// packed-constant maker
#define PKC(d, v) asm("mov.b64 %0, {%1, %1};" : "=l"(d) : "f"(v))

// packed f32x2 exp: magic-round split + degree-4 Taylor of 2^f on [-0.5,0.5].
__device__ __forceinline__ void fexp_pk(
    float& x0, float& x1,
    unsigned long long L2E, unsigned long long MAG, unsigned long long NMAG,
    unsigned long long N1,  unsigned long long C4,  unsigned long long C3,
    unsigned long long C2,  unsigned long long C1,  unsigned long long C0) {
    unsigned long long X, Y, R, T, F, P;
    asm("mov.b64 %0, {%1, %2};" : "=l"(X) : "f"(x0), "f"(x1));
    asm("mul.rn.f32x2 %0, %1, %2;" : "=l"(Y) : "l"(X), "l"(L2E));
    asm("add.rn.f32x2 %0, %1, %2;" : "=l"(R) : "l"(Y), "l"(MAG));
    unsigned int r0, r1;
    asm("mov.b64 {%0, %1}, %2;" : "=r"(r0), "=r"(r1) : "l"(R));
    asm("add.rn.f32x2 %0, %1, %2;" : "=l"(T) : "l"(R), "l"(NMAG));
    asm("fma.rn.f32x2 %0, %1, %2, %3;" : "=l"(F) : "l"(T), "l"(N1), "l"(Y));
    asm("fma.rn.f32x2 %0, %1, %2, %3;" : "=l"(P) : "l"(C4), "l"(F), "l"(C3));
    asm("fma.rn.f32x2 %0, %1, %2, %3;" : "=l"(P) : "l"(P), "l"(F), "l"(C2));
    asm("fma.rn.f32x2 %0, %1, %2, %3;" : "=l"(P) : "l"(P), "l"(F), "l"(C1));
    asm("fma.rn.f32x2 %0, %1, %2, %3;" : "=l"(P) : "l"(P), "l"(F), "l"(C0));
    unsigned int p0, p1;
    asm("mov.b64 {%0, %1}, %2;" : "=r"(p0), "=r"(p1) : "l"(P));
    const int i0 = (int)(r0 - 0x4B400000u);
    const int i1 = (int)(r1 - 0x4B400000u);
    x0 = __int_as_float((int)p0 + (i0 << 23));
    x1 = __int_as_float((int)p1 + (i1 << 23));
}

// ---------------- tiling ----------------
#define BM 128
#define BN 128
#define BK 32
#define ROWB 96
#define TILE_BYTES (128 * ROWB)
#define STAGE_BYTES (2 * TILE_BYTES)
#define NSTAGE 3
#define SMEM_MAIN (NSTAGE * STAGE_BYTES)     // 73728
#define SMEM_TOT  (SMEM_MAIN + 1024)         // 74752

// ================= shared mainloop (R8-exact ordering) =================
#define MAINLOOP_BODY(Aptr_, Bptr_, lda_, ldb_, Kdim_)                                   \
    const int rbase = t >> 2;                                                            \
    const int ch    = t & 3;                                                             \
    const __half* Arow = (Aptr_) + (long long)m0 * (lda_) + ch * 8;                      \
    const __half* Brow = (Bptr_) + (long long)n0 * (ldb_) + ch * 8;                      \
    auto issue = [&](int c, int buf) {                                                   \
        const int k0 = c * BK;                                                           \
        const uint32_t da = sbase + (uint32_t)buf * STAGE_BYTES;                         \
        const uint32_t db = da + TILE_BYTES;                                             \
        _Pragma("unroll")                                                                \
        for (int i = 0; i < 4; i++) {                                                    \
            const int r = rbase + 32 * i;                                                \
            cpa16(da + r * ROWB + ch * 16, Arow + (long long)r * (lda_) + k0);           \
            cpa16(db + r * ROWB + ch * 16, Brow + (long long)r * (ldb_) + k0);           \
        }                                                                                \
    };                                                                                   \
    const int nchunk = (Kdim_) >> 5;                                                     \
    issue(0, 0); CP_COMMIT();                                                            \
    issue(1, 1); CP_COMMIT();                                                            \
    issue(2, 2); CP_COMMIT();                                                            \
    for (int c = 0; c < nchunk; c++) {                                                   \
        const int buf = c % NSTAGE;                                                      \
        CP_WAIT2();                                                                      \
        __syncthreads();                                                                 \
        const char* As = smem + buf * STAGE_BYTES;                                       \
        const char* Bs = As + TILE_BYTES;                                                \
        _Pragma("unroll")                                                                \
        for (int ks = 0; ks < 2; ks++) {                                                 \
            const int off = ks * 32 + 8 * fj;                                            \
            uint32_t a[4][4], b[8][2];                                                   \
            _Pragma("unroll")                                                            \
            for (int ma = 0; ma < 4; ma++) {                                             \
                const char* pr = As + (wm + 16 * ma + fr) * ROWB + off;                  \
                uint2 lo = *reinterpret_cast<const uint2*>(pr);                          \
                uint2 hi = *reinterpret_cast<const uint2*>(pr + 8 * ROWB);               \
                a[ma][0] = lo.x; a[ma][2] = lo.y;                                        \
                a[ma][1] = hi.x; a[ma][3] = hi.y;                                        \
            }                                                                            \
            _Pragma("unroll")                                                            \
            for (int na = 0; na < 8; na++) {                                             \
                uint2 v = *reinterpret_cast<const uint2*>(                               \
                    Bs + (wn + 8 * na + fr) * ROWB + off);                               \
                b[na][0] = v.x; b[na][1] = v.y;                                          \
            }                                                                            \
            _Pragma("unroll")                                                            \
            for (int ma = 0; ma < 4; ma++)                                               \
                _Pragma("unroll")                                                        \
                for (int na = 0; na < 8; na++)                                           \
                    mma_f16(acc[ma][na], a[ma], b[na]);                                  \
        }                                                                                \
        __syncthreads();                                                                 \
        if (c + NSTAGE < nchunk) issue(c + NSTAGE, buf);                                 \
        CP_COMMIT();                                                                     \
    }

// ---------------- merged projection kernel: z selects Q/K/V (2 CTAs/SM) ------------
__global__ __launch_bounds__(128, 2)
void proj_h(const __half* __restrict__ qR, const __half* __restrict__ kR,
            const __half* __restrict__ vR, const __half* __restrict__ Wt,
            const float* __restrict__ bQ, const float* __restrict__ bK,
            const float* __restrict__ bV,
            __half* __restrict__ Qo, __half* __restrict__ Ko, __half* __restrict__ Vto) {
    extern __shared__ char smem[];
    const uint32_t sbase = smem_u32(smem);

    const int t    = threadIdx.x;
    const int lane = t & 31;
    const int w    = t >> 5;
    const int wm   = (w & 1) * 64;
    const int wn   = (w >> 1) * 64;
    const int m0   = blockIdx.y * BM;
    const int n0   = blockIdx.x * BN;
    const int z    = blockIdx.z;

    const __half* A    = (z == 0) ? qR : (z == 1) ? kR : vR;
    const __half* B    = Wt + (size_t)z * DIM * DIM;
    const float*  bias = (z == 0) ? bQ : (z == 1) ? bK : bV;
    const float   alpha = (z == 0) ? SM_SCALE : 1.0f;

    float acc[4][8][4];
#pragma unroll
    for (int i = 0; i < 4; i++)
#pragma unroll
        for (int j = 0; j < 8; j++)
#pragma unroll
            for (int q = 0; q < 4; q++) acc[i][j][q] = 0.0f;

    const int fr = lane >> 2;
    const int fj = lane & 3;

    MAINLOOP_BODY(A, B, DIM, DIM, DIM)

    const int fp = 2 * fj;
#pragma unroll
    for (int ma = 0; ma < 4; ma++) {
        const int r0 = m0 + wm + ma * 16 + fr;
#pragma unroll
        for (int na = 0; na < 8; na++) {
            const int col = n0 + wn + na * 8 + fp;
            const float b0 = bias[col], b1 = bias[col + 1];
            float v0 = (acc[ma][na][0] + b0) * alpha;
            float v1 = (acc[ma][na][1] + b1) * alpha;
            float v2 = (acc[ma][na][2] + b0) * alpha;
            float v3 = (acc[ma][na][3] + b1) * alpha;
            if (z == 2) {
                const int tokb = (r0 & (NTOK - 1)) & ~15;
                const int tp   = pos16(r0 & 15);
                __half* o = Vto + (long long)(r0 >> 12) * ((long long)DIM * NTOK);
                o[(long long)col * NTOK + tokb + tp]           = __float2half_rn(v0);
                o[(long long)(col + 1) * NTOK + tokb + tp]     = __float2half_rn(v1);
                o[(long long)col * NTOK + tokb + tp + 2]       = __float2half_rn(v2);
                o[(long long)(col + 1) * NTOK + tokb + tp + 2] = __float2half_rn(v3);
            } else {
                const int scol = (col & ~15) | pos16(col & 15);
                __half* o = (z == 0) ? Qo : Ko;
                *reinterpret_cast<__half2*>(o + (long long)r0 * DIM + scol) =
                    __floats2half2_rn(v0, v1);
                *reinterpret_cast<__half2*>(o + (long long)(r0 + 8) * DIM + scol) =
                    __floats2half2_rn(v2, v3);
            }
        }
    }
}

// ---------------- scores kernel (3 CTAs/SM): exp fused + partial row sums ----------
__global__ __launch_bounds__(128, 3)
void scores_h(const __half* __restrict__ Qg, const __half* __restrict__ Kg,
              __half* __restrict__ Sg, float* __restrict__ part) {
    extern __shared__ char smem[];
    const uint32_t sbase = smem_u32(smem);

    const int t    = threadIdx.x;
    const int lane = t & 31;
    const int w    = t >> 5;
    const int wm   = (w & 1) * 64;
    const int wn   = (w >> 1) * 64;
    const int m0   = blockIdx.y * BM;
    const int n0   = blockIdx.x * BN;
    const int bz   = blockIdx.z;

    const __half* A = Qg + (long long)bz * NTOK * DIM;
    const __half* B = Kg + (long long)bz * NTOK * DIM;

    float acc[4][8][4];
#pragma unroll
    for (int i = 0; i < 4; i++)
#pragma unroll
        for (int j = 0; j < 8; j++)
#pragma unroll
            for (int q = 0; q < 4; q++) acc[i][j][q] = 0.0f;

    const int fr = lane >> 2;
    const int fj = lane & 3;

    MAINLOOP_BODY(A, B, DIM, DIM, DIM)

    unsigned long long L2E, MAG, NMAG, N1, C4, C3, C2, C1, C0;
    PKC(L2E, 1.4426950408889634f);
    PKC(MAG, 12582912.0f);
    PKC(NMAG, -12582912.0f);
    PKC(N1, -1.0f);
    PKC(C4, 0.0096181291f);
    PKC(C3, 0.0555041087f);
    PKC(C2, 0.2402265069f);
    PKC(C1, 0.6931471806f);
    PKC(C0, 1.0f);

    const int fp = 2 * fj;
    float rs[4][2];
#pragma unroll
    for (int i = 0; i < 4; i++) { rs[i][0] = 0.0f; rs[i][1] = 0.0f; }

    __half* So = Sg + (long long)bz * NTOK * NTOK;
#pragma unroll
    for (int ma = 0; ma < 4; ma++) {
        const int r0 = m0 + wm + ma * 16 + fr;
#pragma unroll
        for (int na = 0; na < 8; na++) {
            const int col = n0 + wn + na * 8 + fp;
            float v0 = acc[ma][na][0], v1 = acc[ma][na][1];
            float v2 = acc[ma][na][2], v3 = acc[ma][na][3];
            fexp_pk(v0, v1, L2E, MAG, NMAG, N1, C4, C3, C2, C1, C0);
            fexp_pk(v2, v3, L2E, MAG, NMAG, N1, C4, C3, C2, C1, C0);
            rs[ma][0] += v0 + v1;
            rs[ma][1] += v2 + v3;
            const int scol = (col & ~15) | pos16(col & 15);
            *reinterpret_cast<__half2*>(So + (long long)r0 * NTOK + scol) =
                __floats2half2_rn(v0, v1);
            *reinterpret_cast<__half2*>(So + (long long)(r0 + 8) * NTOK + scol) =
                __floats2half2_rn(v2, v3);
        }
    }

    float (*spart)[2] = reinterpret_cast<float (*)[2]>(smem + SMEM_MAIN);
    const int wgrp = w >> 1;
    __syncthreads();
#pragma unroll
    for (int ma = 0; ma < 4; ma++) {
        float s0 = rs[ma][0], s1 = rs[ma][1];
        s0 += __shfl_xor_sync(0xFFFFFFFF, s0, 1);
        s0 += __shfl_xor_sync(0xFFFFFFFF, s0, 2);
        s1 += __shfl_xor_sync(0xFFFFFFFF, s1, 1);
        s1 += __shfl_xor_sync(0xFFFFFFFF, s1, 2);
        if (fj == 0) {
            spart[wm + 16 * ma + fr][wgrp]     = s0;
            spart[wm + 16 * ma + fr + 8][wgrp] = s1;
        }
    }
    __syncthreads();
    if (t < 128) {
        const float s = spart[t][0] + spart[t][1];
        part[((long long)bz * NCOLBLK + blockIdx.x) * NTOK + m0 + t] = s;
    }
}

// ---------------- AV kernel (3 CTAs/SM): normalized fp32 out ----------------
__global__ __launch_bounds__(128, 3)
void av_h(const __half* __restrict__ Sg, const __half* __restrict__ Vtg,
          float* __restrict__ Og, const float* __restrict__ part) {
    extern __shared__ char smem[];
    const uint32_t sbase = smem_u32(smem);

    const int t    = threadIdx.x;
    const int lane = t & 31;
    const int w    = t >> 5;
    const int wm   = (w & 1) * 64;
    const int wn   = (w >> 1) * 64;
    const int m0   = blockIdx.y * BM;
    const int n0   = blockIdx.x * BN;
    const int bz   = blockIdx.z;

    const __half* A = Sg + (long long)bz * NTOK * NTOK;
    const __half* B = Vtg + (long long)bz * DIM * NTOK;

    float* invs = reinterpret_cast<float*>(smem + SMEM_MAIN);
    {
        float s = 0.0f;
        if (t < 128) {
#pragma unroll
            for (int k = 0; k < NCOLBLK; k++)
                s += part[((long long)bz * NCOLBLK + k) * NTOK + m0 + t];
            invs[t] = 1.0f / s;
        }
        __syncthreads();
    }

    float acc[4][8][4];
#pragma unroll
    for (int i = 0; i < 4; i++)
#pragma unroll
        for (int j = 0; j < 8; j++)
#pragma unroll
            for (int q = 0; q < 4; q++) acc[i][j][q] = 0.0f;

    const int fr = lane >> 2;
    const int fj = lane & 3;

    MAINLOOP_BODY(A, B, NTOK, NTOK, NTOK)

    const int fp = 2 * fj;
    float* Oo = Og + (long long)bz * NTOK * DIM;
#pragma unroll
    for (int ma = 0; ma < 4; ma++) {
        const int r0 = m0 + wm + ma * 16 + fr;
        const float i0 = invs[wm + 16 * ma + fr];
        const float i1 = invs[wm + 16 * ma + fr + 8];
#pragma unroll
        for (int na = 0; na < 8; na++) {
            const int col = n0 + wn + na * 8 + fp;
            *reinterpret_cast<float2*>(Oo + (long long)r0 * DIM + col) =
                make_float2(acc[ma][na][0] * i0, acc[ma][na][1] * i0);
            *reinterpret_cast<float2*>(Oo + (long long)(r0 + 8) * DIM + col) =
                make_float2(acc[ma][na][2] * i1, acc[ma][na][3] * i1);
        }
    }
}

// ---------------- merged input prepass (grid.y selects input) ----------------
__global__ __launch_bounds__(256)
void prep_h3(const float* __restrict__ i0, const float* __restrict__ i1,
             const float* __restrict__ i2,
             __half* __restrict__ o0, __half* __restrict__ o1,
             __half* __restrict__ o2, int n16) {
    int i = blockIdx.x * 256 + threadIdx.x;
    if (i >= n16) return;
    const float* in  = (blockIdx.y == 0) ? i0 : (blockIdx.y == 1) ? i1 : i2;
    __half*      out = (blockIdx.y == 0) ? o0 : (blockIdx.y == 1) ? o1 : o2;
    const float4* p = reinterpret_cast<const float4*>(in) + 4 * (size_t)i;
    float L[16];
    *reinterpret_cast<float4*>(L)      = p[0];
    *reinterpret_cast<float4*>(L + 4)  = p[1];
    *reinterpret_cast<float4*>(L + 8)  = p[2];
    *reinterpret_cast<float4*>(L + 12) = p[3];
    __half2 h[8];
#pragma unroll
    for (int tt = 0; tt < 4; tt++) {
        h[2 * tt]     = __floats2half2_rn(L[2 * tt],     L[2 * tt + 1]);
        h[2 * tt + 1] = __floats2half2_rn(L[2 * tt + 8], L[2 * tt + 9]);
    }
    uint4* o = reinterpret_cast<uint4*>(out + 16 * (size_t)i);
    o[0] = *reinterpret_cast<uint4*>(h);
    o[1] = *reinterpret_cast<uint4*>(h + 4);
}

// ---------------- merged weight transpose (grid.z selects weight) ----------------
__global__ void transpose512h3(const float* __restrict__ w0, const float* __restrict__ w1,
                               const float* __restrict__ w2, __half* __restrict__ out) {
    __shared__ float tile[32][33];
    const float* in = (blockIdx.z == 0) ? w0 : (blockIdx.z == 1) ? w1 : w2;
    __half* o = out + (size_t)blockIdx.z * DIM * DIM;
    int x = blockIdx.x * 32 + threadIdx.x;
    int y0 = blockIdx.y * 32;
#pragma unroll
    for (int j = threadIdx.y; j < 32; j += 8)
        tile[j][threadIdx.x] = in[(size_t)(y0 + j) * 512 + x];
    __syncthreads();
    int ox = y0 + threadIdx.x;
    int sx = (ox & ~15) | pos16(ox & 15);
    int oy0 = blockIdx.x * 32;
#pragma unroll
    for (int j = threadIdx.y; j < 32; j += 8)
        o[(size_t)(oy0 + j) * 512 + sx] = __float2half_rn(tile[threadIdx.x][j]);
}

// ---------------- launch ----------------
extern "C" void kernel_launch(void* const* d_in, const int* in_sizes, int n_in,
                              void* d_out, int out_size) {
    const float* qX  = (const float*)d_in[0];
    const float* kX  = (const float*)d_in[1];
    const float* vX  = (const float*)d_in[2];
    const float* W_Q = (const float*)d_in[3];
    const float* b_Q = (const float*)d_in[4];
    const float* W_K = (const float*)d_in[5];
    const float* b_K = (const float*)d_in[6];
    const float* W_V = (const float*)d_in[7];
    const float* b_V = (const float*)d_in[8];
    float* out = (float*)d_out;

    __half *Q, *K, *Vt, *S, *Wt;
    float* part;
    cudaGetSymbolAddress((void**)&Q,    g_Q);
    cudaGetSymbolAddress((void**)&K,    g_K);
    cudaGetSymbolAddress((void**)&Vt,   g_Vt);
    cudaGetSymbolAddress((void**)&S,    g_S);
    cudaGetSymbolAddress((void**)&Wt,   g_Wt);
    cudaGetSymbolAddress((void**)&part, g_part);

    cudaFuncSetAttribute(proj_h,   cudaFuncAttributeMaxDynamicSharedMemorySize, SMEM_TOT);
    cudaFuncSetAttribute(scores_h, cudaFuncAttributeMaxDynamicSharedMemorySize, SMEM_TOT);
    cudaFuncSetAttribute(av_h,     cudaFuncAttributeMaxDynamicSharedMemorySize, SMEM_TOT);

    const size_t nin = (size_t)MTOT * DIM;
    __half* qR = S;
    __half* kR = S + nin;
    __half* vR = S + 2 * nin;

    // 0) prepass inputs (one launch) + weights (one launch)
    {
        int n16 = (int)(nin / 16);
        dim3 pg((n16 + 255) / 256, 3, 1);
        prep_h3<<<pg, 256>>>(qX, kX, vX, qR, kR, vR, n16);
        dim3 g(16, 16, 3), b(32, 8);
        transpose512h3<<<g, b>>>(W_Q, W_K, W_V, Wt);
    }

    // 1) all three projections in one launch (z = 0:Q, 1:K, 2:V-transposed)
    {
        dim3 grid(DIM / BN, MTOT / BM, 3);
        proj_h<<<grid, 128, SMEM_TOT>>>(qR, kR, vR, Wt, b_Q, b_K, b_V, Q, K, Vt);
    }

    // 2) scores + fused exp + partial row sums
    {
        dim3 grid(NTOK / BN, NTOK / BM, NBATCH);
        scores_h<<<grid, 128, SMEM_TOT>>>(Q, K, S, part);
    }

    // 3) out = (E @ Vt^T) / rowsum
    {
        dim3 grid(DIM / BN, NTOK / BM, NBATCH);
        av_h<<<grid, 128, SMEM_TOT>>>(S, Vt, out, part);
    }
}

// round 15
// speedup vs baseline: 1.0628x; 1.0628x over previous
#include <cuda_runtime.h>
#include <cuda_fp16.h>
#include <cstdint>

#define NBATCH 4
#define NTOK   4096
#define DIM    512
#define MTOT   (NBATCH * NTOK)
#define SM_SCALE 0.044194173824159216f   // 1/sqrt(512)
#define NCOLBLK (NTOK / 128)             // 32 scores column blocks

// ---------------- scratch (half precision) ----------------
__device__ __half g_Q [(size_t)MTOT * DIM];            // 16 MB, cols perm16, pre-scaled
__device__ __half g_K [(size_t)MTOT * DIM];            // 16 MB, cols perm16
__device__ __half g_Vt[(size_t)MTOT * DIM];            // 16 MB, per-batch [dim][tok], tok perm16
__device__ __half g_S [(size_t)NBATCH * NTOK * NTOK];  // 134 MB (hosts prepped inputs pre-scores)
__device__ __half g_Wt[3ULL * DIM * DIM];              // 1.5 MB transposed + perm16
__device__ float  g_part[(size_t)NBATCH * NCOLBLK * NTOK];  // 2 MB partial row sums of exp(S)

// ---------------- helpers ----------------
__device__ __forceinline__ int pos16(int j) {
    return ((j & 6) << 1) | ((j & 8) >> 2) | (j & 1);
}
__device__ __forceinline__ void mma_f16(float* d, const uint32_t* a, const uint32_t* b) {
    asm volatile(
        "mma.sync.aligned.m16n8k16.row.col.f32.f16.f16.f32 "
        "{%0,%1,%2,%3}, {%4,%5,%6,%7}, {%8,%9}, {%0,%1,%2,%3};"
        : "+f"(d[0]), "+f"(d[1]), "+f"(d[2]), "+f"(d[3])
        : "r"(a[0]), "r"(a[1]), "r"(a[2]), "r"(a[3]), "r"(b[0]), "r"(b[1]));
}
__device__ __forceinline__ uint32_t smem_u32(const void* p) {
    uint32_t r;
    asm("{ .reg .u64 t; cvta.to.shared.u64 t, %1; cvt.u32.u64 %0, t; }" : "=r"(r) : "l"(p));
    return r;
}
__device__ __forceinline__ void cpa16(uint32_t dst, const void* src) {
    asm volatile("cp.async.cg.shared.global [%0], [%1], 16;" :: "r"(dst), "l"(src));
}
#define CP_COMMIT() asm volatile("cp.async.commit_group;" ::: "memory")
#define CP_WAIT1()  asm volatile("cp.async.wait_group 1;" ::: "memory")

// packed-constant maker
#define PKC(d, v) asm("mov.b64 %0, {%1, %1};" : "=l"(d) : "f"(v))

// packed f32x2 exp: magic-round split + degree-4 Taylor of 2^f on [-0.5,0.5].
__device__ __forceinline__ void fexp_pk(
    float& x0, float& x1,
    unsigned long long L2E, unsigned long long MAG, unsigned long long NMAG,
    unsigned long long N1,  unsigned long long C4,  unsigned long long C3,
    unsigned long long C2,  unsigned long long C1,  unsigned long long C0) {
    unsigned long long X, Y, R, T, F, P;
    asm("mov.b64 %0, {%1, %2};" : "=l"(X) : "f"(x0), "f"(x1));
    asm("mul.rn.f32x2 %0, %1, %2;" : "=l"(Y) : "l"(X), "l"(L2E));
    asm("add.rn.f32x2 %0, %1, %2;" : "=l"(R) : "l"(Y), "l"(MAG));
    unsigned int r0, r1;
    asm("mov.b64 {%0, %1}, %2;" : "=r"(r0), "=r"(r1) : "l"(R));
    asm("add.rn.f32x2 %0, %1, %2;" : "=l"(T) : "l"(R), "l"(NMAG));
    asm("fma.rn.f32x2 %0, %1, %2, %3;" : "=l"(F) : "l"(T), "l"(N1), "l"(Y));
    asm("fma.rn.f32x2 %0, %1, %2, %3;" : "=l"(P) : "l"(C4), "l"(F), "l"(C3));
    asm("fma.rn.f32x2 %0, %1, %2, %3;" : "=l"(P) : "l"(P), "l"(F), "l"(C2));
    asm("fma.rn.f32x2 %0, %1, %2, %3;" : "=l"(P) : "l"(P), "l"(F), "l"(C1));
    asm("fma.rn.f32x2 %0, %1, %2, %3;" : "=l"(P) : "l"(P), "l"(F), "l"(C0));
    unsigned int p0, p1;
    asm("mov.b64 {%0, %1}, %2;" : "=r"(p0), "=r"(p1) : "l"(P));
    const int i0 = (int)(r0 - 0x4B400000u);
    const int i1 = (int)(r1 - 0x4B400000u);
    x0 = __int_as_float((int)p0 + (i0 << 23));
    x1 = __int_as_float((int)p1 + (i1 << 23));
}

// ---------------- tiling ----------------
#define BM 128
#define BN 128
#define BK 32
#define ROWB 96
#define TILE_BYTES (128 * ROWB)
#define STAGE_BYTES (2 * TILE_BYTES)
#define NSTAGE 3
#define SMEM_MAIN (NSTAGE * STAGE_BYTES)     // 73728
#define SMEM_TOT  (SMEM_MAIN + 1024)         // 74752

// ================= shared mainloop: single-barrier, 3 buffers, commit 2-ahead =====
// issue(c+2) writes buf (c+2)%3 — last read at iter c-1, ordered by the iter-c barrier.
#define MAINLOOP_BODY(Aptr_, Bptr_, lda_, ldb_, Kdim_)                                   \
    const int rbase = t >> 2;                                                            \
    const int ch    = t & 3;                                                             \
    const __half* Arow = (Aptr_) + (long long)m0 * (lda_) + ch * 8;                      \
    const __half* Brow = (Bptr_) + (long long)n0 * (ldb_) + ch * 8;                      \
    auto issue = [&](int c, int buf) {                                                   \
        const int k0 = c * BK;                                                           \
        const uint32_t da = sbase + (uint32_t)buf * STAGE_BYTES;                         \
        const uint32_t db = da + TILE_BYTES;                                             \
        _Pragma("unroll")                                                                \
        for (int i = 0; i < 4; i++) {                                                    \
            const int r = rbase + 32 * i;                                                \
            cpa16(da + r * ROWB + ch * 16, Arow + (long long)r * (lda_) + k0);           \
            cpa16(db + r * ROWB + ch * 16, Brow + (long long)r * (ldb_) + k0);           \
        }                                                                                \
    };                                                                                   \
    const int nchunk = (Kdim_) >> 5;                                                     \
    issue(0, 0); CP_COMMIT();                                                            \
    issue(1, 1); CP_COMMIT();                                                            \
    for (int c = 0; c < nchunk; c++) {                                                   \
        const int buf = c % NSTAGE;                                                      \
        CP_WAIT1();                                                                      \
        __syncthreads();                                                                 \
        const char* As = smem + buf * STAGE_BYTES;                                       \
        const char* Bs = As + TILE_BYTES;                                                \
        _Pragma("unroll")                                                                \
        for (int ks = 0; ks < 2; ks++) {                                                 \
            const int off = ks * 32 + 8 * fj;                                            \
            uint32_t a[4][4], b[8][2];                                                   \
            _Pragma("unroll")                                                            \
            for (int ma = 0; ma < 4; ma++) {                                             \
                const char* pr = As + (wm + 16 * ma + fr) * ROWB + off;                  \
                uint2 lo = *reinterpret_cast<const uint2*>(pr);                          \
                uint2 hi = *reinterpret_cast<const uint2*>(pr + 8 * ROWB);               \
                a[ma][0] = lo.x; a[ma][2] = lo.y;                                        \
                a[ma][1] = hi.x; a[ma][3] = hi.y;                                        \
            }                                                                            \
            _Pragma("unroll")                                                            \
            for (int na = 0; na < 8; na++) {                                             \
                uint2 v = *reinterpret_cast<const uint2*>(                               \
                    Bs + (wn + 8 * na + fr) * ROWB + off);                               \
                b[na][0] = v.x; b[na][1] = v.y;                                          \
            }                                                                            \
            _Pragma("unroll")                                                            \
            for (int ma = 0; ma < 4; ma++)                                               \
                _Pragma("unroll")                                                        \
                for (int na = 0; na < 8; na++)                                           \
                    mma_f16(acc[ma][na], a[ma], b[na]);                                  \
        }                                                                                \
        if (c + 2 < nchunk) issue(c + 2, (c + 2) % NSTAGE);                              \
        CP_COMMIT();                                                                     \
    }

// ---------------- merged projection kernel: z selects Q/K/V (2 CTAs/SM) ------------
__global__ __launch_bounds__(128, 2)
void proj_h(const __half* __restrict__ qR, const __half* __restrict__ kR,
            const __half* __restrict__ vR, const __half* __restrict__ Wt,
            const float* __restrict__ bQ, const float* __restrict__ bK,
            const float* __restrict__ bV,
            __half* __restrict__ Qo, __half* __restrict__ Ko, __half* __restrict__ Vto) {
    extern __shared__ char smem[];
    const uint32_t sbase = smem_u32(smem);

    const int t    = threadIdx.x;
    const int lane = t & 31;
    const int w    = t >> 5;
    const int wm   = (w & 1) * 64;
    const int wn   = (w >> 1) * 64;
    const int m0   = blockIdx.y * BM;
    const int n0   = blockIdx.x * BN;
    const int z    = blockIdx.z;

    const __half* A    = (z == 0) ? qR : (z == 1) ? kR : vR;
    const __half* B    = Wt + (size_t)z * DIM * DIM;
    const float*  bias = (z == 0) ? bQ : (z == 1) ? bK : bV;
    const float   alpha = (z == 0) ? SM_SCALE : 1.0f;

    float acc[4][8][4];
#pragma unroll
    for (int i = 0; i < 4; i++)
#pragma unroll
        for (int j = 0; j < 8; j++)
#pragma unroll
            for (int q = 0; q < 4; q++) acc[i][j][q] = 0.0f;

    const int fr = lane >> 2;
    const int fj = lane & 3;

    MAINLOOP_BODY(A, B, DIM, DIM, DIM)

    const int fp = 2 * fj;
#pragma unroll
    for (int ma = 0; ma < 4; ma++) {
        const int r0 = m0 + wm + ma * 16 + fr;
#pragma unroll
        for (int na = 0; na < 8; na++) {
            const int col = n0 + wn + na * 8 + fp;
            const float b0 = bias[col], b1 = bias[col + 1];
            float v0 = (acc[ma][na][0] + b0) * alpha;
            float v1 = (acc[ma][na][1] + b1) * alpha;
            float v2 = (acc[ma][na][2] + b0) * alpha;
            float v3 = (acc[ma][na][3] + b1) * alpha;
            if (z == 2) {
                const int tokb = (r0 & (NTOK - 1)) & ~15;
                const int tp   = pos16(r0 & 15);
                __half* o = Vto + (long long)(r0 >> 12) * ((long long)DIM * NTOK);
                o[(long long)col * NTOK + tokb + tp]           = __float2half_rn(v0);
                o[(long long)(col + 1) * NTOK + tokb + tp]     = __float2half_rn(v1);
                o[(long long)col * NTOK + tokb + tp + 2]       = __float2half_rn(v2);
                o[(long long)(col + 1) * NTOK + tokb + tp + 2] = __float2half_rn(v3);
            } else {
                const int scol = (col & ~15) | pos16(col & 15);
                __half* o = (z == 0) ? Qo : Ko;
                *reinterpret_cast<__half2*>(o + (long long)r0 * DIM + scol) =
                    __floats2half2_rn(v0, v1);
                *reinterpret_cast<__half2*>(o + (long long)(r0 + 8) * DIM + scol) =
                    __floats2half2_rn(v2, v3);
            }
        }
    }
}

// ---------------- scores kernel (3 CTAs/SM): exp fused + partial row sums ----------
__global__ __launch_bounds__(128, 3)
void scores_h(const __half* __restrict__ Qg, const __half* __restrict__ Kg,
              __half* __restrict__ Sg, float* __restrict__ part) {
    extern __shared__ char smem[];
    const uint32_t sbase = smem_u32(smem);

    const int t    = threadIdx.x;
    const int lane = t & 31;
    const int w    = t >> 5;
    const int wm   = (w & 1) * 64;
    const int wn   = (w >> 1) * 64;
    const int m0   = blockIdx.y * BM;
    const int n0   = blockIdx.x * BN;
    const int bz   = blockIdx.z;

    const __half* A = Qg + (long long)bz * NTOK * DIM;
    const __half* B = Kg + (long long)bz * NTOK * DIM;

    float acc[4][8][4];
#pragma unroll
    for (int i = 0; i < 4; i++)
#pragma unroll
        for (int j = 0; j < 8; j++)
#pragma unroll
            for (int q = 0; q < 4; q++) acc[i][j][q] = 0.0f;

    const int fr = lane >> 2;
    const int fj = lane & 3;

    MAINLOOP_BODY(A, B, DIM, DIM, DIM)

    unsigned long long L2E, MAG, NMAG, N1, C4, C3, C2, C1, C0;
    PKC(L2E, 1.4426950408889634f);
    PKC(MAG, 12582912.0f);
    PKC(NMAG, -12582912.0f);
    PKC(N1, -1.0f);
    PKC(C4, 0.0096181291f);
    PKC(C3, 0.0555041087f);
    PKC(C2, 0.2402265069f);
    PKC(C1, 0.6931471806f);
    PKC(C0, 1.0f);

    const int fp = 2 * fj;
    float rs[4][2];
#pragma unroll
    for (int i = 0; i < 4; i++) { rs[i][0] = 0.0f; rs[i][1] = 0.0f; }

    __half* So = Sg + (long long)bz * NTOK * NTOK;
#pragma unroll
    for (int ma = 0; ma < 4; ma++) {
        const int r0 = m0 + wm + ma * 16 + fr;
#pragma unroll
        for (int na = 0; na < 8; na++) {
            const int col = n0 + wn + na * 8 + fp;
            float v0 = acc[ma][na][0], v1 = acc[ma][na][1];
            float v2 = acc[ma][na][2], v3 = acc[ma][na][3];
            fexp_pk(v0, v1, L2E, MAG, NMAG, N1, C4, C3, C2, C1, C0);
            fexp_pk(v2, v3, L2E, MAG, NMAG, N1, C4, C3, C2, C1, C0);
            rs[ma][0] += v0 + v1;
            rs[ma][1] += v2 + v3;
            const int scol = (col & ~15) | pos16(col & 15);
            *reinterpret_cast<__half2*>(So + (long long)r0 * NTOK + scol) =
                __floats2half2_rn(v0, v1);
            *reinterpret_cast<__half2*>(So + (long long)(r0 + 8) * NTOK + scol) =
                __floats2half2_rn(v2, v3);
        }
    }

    float (*spart)[2] = reinterpret_cast<float (*)[2]>(smem + SMEM_MAIN);
    const int wgrp = w >> 1;
    __syncthreads();
#pragma unroll
    for (int ma = 0; ma < 4; ma++) {
        float s0 = rs[ma][0], s1 = rs[ma][1];
        s0 += __shfl_xor_sync(0xFFFFFFFF, s0, 1);
        s0 += __shfl_xor_sync(0xFFFFFFFF, s0, 2);
        s1 += __shfl_xor_sync(0xFFFFFFFF, s1, 1);
        s1 += __shfl_xor_sync(0xFFFFFFFF, s1, 2);
        if (fj == 0) {
            spart[wm + 16 * ma + fr][wgrp]     = s0;
            spart[wm + 16 * ma + fr + 8][wgrp] = s1;
        }
    }
    __syncthreads();
    if (t < 128) {
        const float s = spart[t][0] + spart[t][1];
        part[((long long)bz * NCOLBLK + blockIdx.x) * NTOK + m0 + t] = s;
    }
}

// ---------------- AV kernel (2 CTAs/SM): normalized fp32 out ----------------
__global__ __launch_bounds__(128, 2)
void av_h(const __half* __restrict__ Sg, const __half* __restrict__ Vtg,
          float* __restrict__ Og, const float* __restrict__ part) {
    extern __shared__ char smem[];
    const uint32_t sbase = smem_u32(smem);

    const int t    = threadIdx.x;
    const int lane = t & 31;
    const int w    = t >> 5;
    const int wm   = (w & 1) * 64;
    const int wn   = (w >> 1) * 64;
    const int m0   = blockIdx.y * BM;
    const int n0   = blockIdx.x * BN;
    const int bz   = blockIdx.z;

    const __half* A = Sg + (long long)bz * NTOK * NTOK;
    const __half* B = Vtg + (long long)bz * DIM * NTOK;

    float* invs = reinterpret_cast<float*>(smem + SMEM_MAIN);
    {
        float s = 0.0f;
        if (t < 128) {
#pragma unroll
            for (int k = 0; k < NCOLBLK; k++)
                s += part[((long long)bz * NCOLBLK + k) * NTOK + m0 + t];
            invs[t] = 1.0f / s;
        }
        __syncthreads();
    }

    float acc[4][8][4];
#pragma unroll
    for (int i = 0; i < 4; i++)
#pragma unroll
        for (int j = 0; j < 8; j++)
#pragma unroll
            for (int q = 0; q < 4; q++) acc[i][j][q] = 0.0f;

    const int fr = lane >> 2;
    const int fj = lane & 3;

    MAINLOOP_BODY(A, B, NTOK, NTOK, NTOK)

    const int fp = 2 * fj;
    float* Oo = Og + (long long)bz * NTOK * DIM;
#pragma unroll
    for (int ma = 0; ma < 4; ma++) {
        const int r0 = m0 + wm + ma * 16 + fr;
        const float i0 = invs[wm + 16 * ma + fr];
        const float i1 = invs[wm + 16 * ma + fr + 8];
#pragma unroll
        for (int na = 0; na < 8; na++) {
            const int col = n0 + wn + na * 8 + fp;
            *reinterpret_cast<float2*>(Oo + (long long)r0 * DIM + col) =
                make_float2(acc[ma][na][0] * i0, acc[ma][na][1] * i0);
            *reinterpret_cast<float2*>(Oo + (long long)(r0 + 8) * DIM + col) =
                make_float2(acc[ma][na][2] * i1, acc[ma][na][3] * i1);
        }
    }
}

// ---------------- merged input prepass (grid.y selects input) ----------------
__global__ __launch_bounds__(256)
void prep_h3(const float* __restrict__ i0, const float* __restrict__ i1,
             const float* __restrict__ i2,
             __half* __restrict__ o0, __half* __restrict__ o1,
             __half* __restrict__ o2, int n16) {
    int i = blockIdx.x * 256 + threadIdx.x;
    if (i >= n16) return;
    const float* in  = (blockIdx.y == 0) ? i0 : (blockIdx.y == 1) ? i1 : i2;
    __half*      out = (blockIdx.y == 0) ? o0 : (blockIdx.y == 1) ? o1 : o2;
    const float4* p = reinterpret_cast<const float4*>(in) + 4 * (size_t)i;
    float L[16];
    *reinterpret_cast<float4*>(L)      = p[0];
    *reinterpret_cast<float4*>(L + 4)  = p[1];
    *reinterpret_cast<float4*>(L + 8)  = p[2];
    *reinterpret_cast<float4*>(L + 12) = p[3];
    __half2 h[8];
#pragma unroll
    for (int tt = 0; tt < 4; tt++) {
        h[2 * tt]     = __floats2half2_rn(L[2 * tt],     L[2 * tt + 1]);
        h[2 * tt + 1] = __floats2half2_rn(L[2 * tt + 8], L[2 * tt + 9]);
    }
    uint4* o = reinterpret_cast<uint4*>(out + 16 * (size_t)i);
    o[0] = *reinterpret_cast<uint4*>(h);
    o[1] = *reinterpret_cast<uint4*>(h + 4);
}

// ---------------- merged weight transpose (grid.z selects weight) ----------------
__global__ void transpose512h3(const float* __restrict__ w0, const float* __restrict__ w1,
                               const float* __restrict__ w2, __half* __restrict__ out) {
    __shared__ float tile[32][33];
    const float* in = (blockIdx.z == 0) ? w0 : (blockIdx.z == 1) ? w1 : w2;
    __half* o = out + (size_t)blockIdx.z * DIM * DIM;
    int x = blockIdx.x * 32 + threadIdx.x;
    int y0 = blockIdx.y * 32;
#pragma unroll
    for (int j = threadIdx.y; j < 32; j += 8)
        tile[j][threadIdx.x] = in[(size_t)(y0 + j) * 512 + x];
    __syncthreads();
    int ox = y0 + threadIdx.x;
    int sx = (ox & ~15) | pos16(ox & 15);
    int oy0 = blockIdx.x * 32;
#pragma unroll
    for (int j = threadIdx.y; j < 32; j += 8)
        o[(size_t)(oy0 + j) * 512 + sx] = __float2half_rn(tile[threadIdx.x][j]);
}

// ---------------- launch ----------------
extern "C" void kernel_launch(void* const* d_in, const int* in_sizes, int n_in,
                              void* d_out, int out_size) {
    const float* qX  = (const float*)d_in[0];
    const float* kX  = (const float*)d_in[1];
    const float* vX  = (const float*)d_in[2];
    const float* W_Q = (const float*)d_in[3];
    const float* b_Q = (const float*)d_in[4];
    const float* W_K = (const float*)d_in[5];
    const float* b_K = (const float*)d_in[6];
    const float* W_V = (const float*)d_in[7];
    const float* b_V = (const float*)d_in[8];
    float* out = (float*)d_out;

    __half *Q, *K, *Vt, *S, *Wt;
    float* part;
    cudaGetSymbolAddress((void**)&Q,    g_Q);
    cudaGetSymbolAddress((void**)&K,    g_K);
    cudaGetSymbolAddress((void**)&Vt,   g_Vt);
    cudaGetSymbolAddress((void**)&S,    g_S);
    cudaGetSymbolAddress((void**)&Wt,   g_Wt);
    cudaGetSymbolAddress((void**)&part, g_part);

    cudaFuncSetAttribute(proj_h,   cudaFuncAttributeMaxDynamicSharedMemorySize, SMEM_TOT);
    cudaFuncSetAttribute(scores_h, cudaFuncAttributeMaxDynamicSharedMemorySize, SMEM_TOT);
    cudaFuncSetAttribute(av_h,     cudaFuncAttributeMaxDynamicSharedMemorySize, SMEM_TOT);

    const size_t nin = (size_t)MTOT * DIM;
    __half* qR = S;
    __half* kR = S + nin;
    __half* vR = S + 2 * nin;

    // 0) prepass inputs (one launch) + weights (one launch)
    {
        int n16 = (int)(nin / 16);
        dim3 pg((n16 + 255) / 256, 3, 1);
        prep_h3<<<pg, 256>>>(qX, kX, vX, qR, kR, vR, n16);
        dim3 g(16, 16, 3), b(32, 8);
        transpose512h3<<<g, b>>>(W_Q, W_K, W_V, Wt);
    }

    // 1) all three projections in one launch (z = 0:Q, 1:K, 2:V-transposed)
    {
        dim3 grid(DIM / BN, MTOT / BM, 3);
        proj_h<<<grid, 128, SMEM_TOT>>>(qR, kR, vR, Wt, b_Q, b_K, b_V, Q, K, Vt);
    }

    // 2) scores + fused exp + partial row sums
    {
        dim3 grid(NTOK / BN, NTOK / BM, NBATCH);
        scores_h<<<grid, 128, SMEM_TOT>>>(Q, K, S, part);
    }

    // 3) out = (E @ Vt^T) / rowsum
    {
        dim3 grid(DIM / BN, NTOK / BM, NBATCH);
        av_h<<<grid, 128, SMEM_TOT>>>(S, Vt, out, part);
    }
}

// round 16
// speedup vs baseline: 1.1115x; 1.0459x over previous
#include <cuda_runtime.h>
#include <cuda_fp16.h>
#include <cstdint>

#define NBATCH 4
#define NTOK   4096
#define DIM    512
#define MTOT   (NBATCH * NTOK)
#define SM_SCALE 0.044194173824159216f   // 1/sqrt(512)
#define NCOLBLK (NTOK / 128)             // 32 scores column blocks

// ---------------- scratch (half precision) ----------------
__device__ __half g_Q [(size_t)MTOT * DIM];            // 16 MB, cols perm16, pre-scaled
__device__ __half g_K [(size_t)MTOT * DIM];            // 16 MB, cols perm16
__device__ __half g_Vt[(size_t)MTOT * DIM];            // 16 MB, per-batch [dim][tok], tok perm16
__device__ __half g_S [(size_t)NBATCH * NTOK * NTOK];  // 134 MB (hosts prepped inputs pre-scores)
__device__ __half g_Wt[3ULL * DIM * DIM];              // 1.5 MB transposed + perm16
__device__ float  g_part[(size_t)NBATCH * NCOLBLK * NTOK];  // 2 MB partial row sums of exp(S)

// ---------------- helpers ----------------
__device__ __forceinline__ int pos16(int j) {
    return ((j & 6) << 1) | ((j & 8) >> 2) | (j & 1);
}
__device__ __forceinline__ void mma_f16(float* d, const uint32_t* a, const uint32_t* b) {
    asm volatile(
        "mma.sync.aligned.m16n8k16.row.col.f32.f16.f16.f32 "
        "{%0,%1,%2,%3}, {%4,%5,%6,%7}, {%8,%9}, {%0,%1,%2,%3};"
        : "+f"(d[0]), "+f"(d[1]), "+f"(d[2]), "+f"(d[3])
        : "r"(a[0]), "r"(a[1]), "r"(a[2]), "r"(a[3]), "r"(b[0]), "r"(b[1]));
}
__device__ __forceinline__ uint32_t smem_u32(const void* p) {
    uint32_t r;
    asm("{ .reg .u64 t; cvta.to.shared.u64 t, %1; cvt.u32.u64 %0, t; }" : "=r"(r) : "l"(p));
    return r;
}
__device__ __forceinline__ void cpa16(uint32_t dst, const void* src) {
    asm volatile("cp.async.cg.shared.global [%0], [%1], 16;" :: "r"(dst), "l"(src));
}
#define CP_COMMIT() asm volatile("cp.async.commit_group;" ::: "memory")
#define CP_WAIT1()  asm volatile("cp.async.wait_group 1;" ::: "memory")

// packed-constant maker
#define PKC(d, v) asm("mov.b64 %0, {%1, %1};" : "=l"(d) : "f"(v))

// packed f32x2 exp: magic-round split + degree-4 Taylor of 2^f on [-0.5,0.5].
__device__ __forceinline__ void fexp_pk(
    float& x0, float& x1,
    unsigned long long L2E, unsigned long long MAG, unsigned long long NMAG,
    unsigned long long N1,  unsigned long long C4,  unsigned long long C3,
    unsigned long long C2,  unsigned long long C1,  unsigned long long C0) {
    unsigned long long X, Y, R, T, F, P;
    asm("mov.b64 %0, {%1, %2};" : "=l"(X) : "f"(x0), "f"(x1));
    asm("mul.rn.f32x2 %0, %1, %2;" : "=l"(Y) : "l"(X), "l"(L2E));
    asm("add.rn.f32x2 %0, %1, %2;" : "=l"(R) : "l"(Y), "l"(MAG));
    unsigned int r0, r1;
    asm("mov.b64 {%0, %1}, %2;" : "=r"(r0), "=r"(r1) : "l"(R));
    asm("add.rn.f32x2 %0, %1, %2;" : "=l"(T) : "l"(R), "l"(NMAG));
    asm("fma.rn.f32x2 %0, %1, %2, %3;" : "=l"(F) : "l"(T), "l"(N1), "l"(Y));
    asm("fma.rn.f32x2 %0, %1, %2, %3;" : "=l"(P) : "l"(C4), "l"(F), "l"(C3));
    asm("fma.rn.f32x2 %0, %1, %2, %3;" : "=l"(P) : "l"(P), "l"(F), "l"(C2));
    asm("fma.rn.f32x2 %0, %1, %2, %3;" : "=l"(P) : "l"(P), "l"(F), "l"(C1));
    asm("fma.rn.f32x2 %0, %1, %2, %3;" : "=l"(P) : "l"(P), "l"(F), "l"(C0));
    unsigned int p0, p1;
    asm("mov.b64 {%0, %1}, %2;" : "=r"(p0), "=r"(p1) : "l"(P));
    const int i0 = (int)(r0 - 0x4B400000u);
    const int i1 = (int)(r1 - 0x4B400000u);
    x0 = __int_as_float((int)p0 + (i0 << 23));
    x1 = __int_as_float((int)p1 + (i1 << 23));
}

__device__ __forceinline__ uint32_t h2pack(float a, float b) {
    __half2 h = __floats2half2_rn(a, b);
    return *reinterpret_cast<uint32_t*>(&h);
}

// ---------------- tiling ----------------
#define BM 128
#define BN 128
#define BK 32
#define ROWB 96
#define TILE_BYTES (128 * ROWB)
#define STAGE_BYTES (2 * TILE_BYTES)
#define NSTAGE 3
#define SMEM_MAIN (NSTAGE * STAGE_BYTES)     // 73728
#define SMEM_TOT  (SMEM_MAIN + 1024)         // 74752

// ================= shared mainloop: single-barrier, 3 buffers, commit 2-ahead =====
#define MAINLOOP_BODY(Aptr_, Bptr_, lda_, ldb_, Kdim_)                                   \
    const int rbase = t >> 2;                                                            \
    const int ch    = t & 3;                                                             \
    const __half* Arow = (Aptr_) + (long long)m0 * (lda_) + ch * 8;                      \
    const __half* Brow = (Bptr_) + (long long)n0 * (ldb_) + ch * 8;                      \
    auto issue = [&](int c, int buf) {                                                   \
        const int k0 = c * BK;                                                           \
        const uint32_t da = sbase + (uint32_t)buf * STAGE_BYTES;                         \
        const uint32_t db = da + TILE_BYTES;                                             \
        _Pragma("unroll")                                                                \
        for (int i = 0; i < 4; i++) {                                                    \
            const int r = rbase + 32 * i;                                                \
            cpa16(da + r * ROWB + ch * 16, Arow + (long long)r * (lda_) + k0);           \
            cpa16(db + r * ROWB + ch * 16, Brow + (long long)r * (ldb_) + k0);           \
        }                                                                                \
    };                                                                                   \
    const int nchunk = (Kdim_) >> 5;                                                     \
    issue(0, 0); CP_COMMIT();                                                            \
    issue(1, 1); CP_COMMIT();                                                            \
    for (int c = 0; c < nchunk; c++) {                                                   \
        const int buf = c % NSTAGE;                                                      \
        CP_WAIT1();                                                                      \
        __syncthreads();                                                                 \
        const char* As = smem + buf * STAGE_BYTES;                                       \
        const char* Bs = As + TILE_BYTES;                                                \
        _Pragma("unroll")                                                                \
        for (int ks = 0; ks < 2; ks++) {                                                 \
            const int off = ks * 32 + 8 * fj;                                            \
            uint32_t a[4][4], b[8][2];                                                   \
            _Pragma("unroll")                                                            \
            for (int ma = 0; ma < 4; ma++) {                                             \
                const char* pr = As + (wm + 16 * ma + fr) * ROWB + off;                  \
                uint2 lo = *reinterpret_cast<const uint2*>(pr);                          \
                uint2 hi = *reinterpret_cast<const uint2*>(pr + 8 * ROWB);               \
                a[ma][0] = lo.x; a[ma][2] = lo.y;                                        \
                a[ma][1] = hi.x; a[ma][3] = hi.y;                                        \
            }                                                                            \
            _Pragma("unroll")                                                            \
            for (int na = 0; na < 8; na++) {                                             \
                uint2 v = *reinterpret_cast<const uint2*>(                               \
                    Bs + (wn + 8 * na + fr) * ROWB + off);                               \
                b[na][0] = v.x; b[na][1] = v.y;                                          \
            }                                                                            \
            _Pragma("unroll")                                                            \
            for (int ma = 0; ma < 4; ma++)                                               \
                _Pragma("unroll")                                                        \
                for (int na = 0; na < 8; na++)                                           \
                    mma_f16(acc[ma][na], a[ma], b[na]);                                  \
        }                                                                                \
        if (c + 2 < nchunk) issue(c + 2, (c + 2) % NSTAGE);                              \
        CP_COMMIT();                                                                     \
    }

// ---------------- merged projection kernel: z selects Q/K/V (2 CTAs/SM) ------------
__global__ __launch_bounds__(128, 2)
void proj_h(const __half* __restrict__ qR, const __half* __restrict__ kR,
            const __half* __restrict__ vR, const __half* __restrict__ Wt,
            const float* __restrict__ bQ, const float* __restrict__ bK,
            const float* __restrict__ bV,
            __half* __restrict__ Qo, __half* __restrict__ Ko, __half* __restrict__ Vto) {
    extern __shared__ char smem[];
    const uint32_t sbase = smem_u32(smem);

    const int t    = threadIdx.x;
    const int lane = t & 31;
    const int w    = t >> 5;
    const int wm   = (w & 1) * 64;
    const int wn   = (w >> 1) * 64;
    const int m0   = blockIdx.y * BM;
    const int n0   = blockIdx.x * BN;
    const int z    = blockIdx.z;

    const __half* A    = (z == 0) ? qR : (z == 1) ? kR : vR;
    const __half* B    = Wt + (size_t)z * DIM * DIM;
    const float*  bias = (z == 0) ? bQ : (z == 1) ? bK : bV;
    const float   alpha = (z == 0) ? SM_SCALE : 1.0f;

    float acc[4][8][4];
#pragma unroll
    for (int i = 0; i < 4; i++)
#pragma unroll
        for (int j = 0; j < 8; j++)
#pragma unroll
            for (int q = 0; q < 4; q++) acc[i][j][q] = 0.0f;

    const int fr = lane >> 2;
    const int fj = lane & 3;

    MAINLOOP_BODY(A, B, DIM, DIM, DIM)

    const int fp = 2 * fj;
#pragma unroll
    for (int ma = 0; ma < 4; ma++) {
        const int r0 = m0 + wm + ma * 16 + fr;
        if (z == 2) {
#pragma unroll
            for (int na = 0; na < 8; na++) {
                const int col = n0 + wn + na * 8 + fp;
                const float b0 = bias[col], b1 = bias[col + 1];
                float v0 = acc[ma][na][0] + b0;
                float v1 = acc[ma][na][1] + b1;
                float v2 = acc[ma][na][2] + b0;
                float v3 = acc[ma][na][3] + b1;
                const int tokb = (r0 & (NTOK - 1)) & ~15;
                const int tp   = pos16(r0 & 15);
                __half* o = Vto + (long long)(r0 >> 12) * ((long long)DIM * NTOK);
                o[(long long)col * NTOK + tokb + tp]           = __float2half_rn(v0);
                o[(long long)(col + 1) * NTOK + tokb + tp]     = __float2half_rn(v1);
                o[(long long)col * NTOK + tokb + tp + 2]       = __float2half_rn(v2);
                o[(long long)(col + 1) * NTOK + tokb + tp + 2] = __float2half_rn(v3);
            }
        } else {
            __half* o = (z == 0) ? Qo : Ko;
#pragma unroll
            for (int nb = 0; nb < 4; nb++) {           // na = 2*nb (even), 2*nb+1 (odd)
                const int ce = n0 + wn + nb * 16 + fp;       // even-atom logical col
                const int co = ce + 8;                       // odd-atom logical col
                const float be0 = bias[ce], be1 = bias[ce + 1];
                const float bo0 = bias[co], bo1 = bias[co + 1];
                float e0 = (acc[ma][2*nb][0] + be0) * alpha;
                float e1 = (acc[ma][2*nb][1] + be1) * alpha;
                float e2 = (acc[ma][2*nb][2] + be0) * alpha;
                float e3 = (acc[ma][2*nb][3] + be1) * alpha;
                float o0 = (acc[ma][2*nb+1][0] + bo0) * alpha;
                float o1 = (acc[ma][2*nb+1][1] + bo1) * alpha;
                float o2 = (acc[ma][2*nb+1][2] + bo0) * alpha;
                float o3 = (acc[ma][2*nb+1][3] + bo1) * alpha;
                // contiguous 4-half run at group base + 4*fj (perm16 layout)
                const long long gb = (long long)(n0 + wn + nb * 16 + 4 * fj);
                *reinterpret_cast<uint2*>(o + (long long)r0 * DIM + gb) =
                    make_uint2(h2pack(e0, e1), h2pack(o0, o1));
                *reinterpret_cast<uint2*>(o + (long long)(r0 + 8) * DIM + gb) =
                    make_uint2(h2pack(e2, e3), h2pack(o2, o3));
            }
        }
    }
}

// ---------------- scores kernel (3 CTAs/SM): exp fused + partial row sums ----------
__global__ __launch_bounds__(128, 3)
void scores_h(const __half* __restrict__ Qg, const __half* __restrict__ Kg,
              __half* __restrict__ Sg, float* __restrict__ part) {
    extern __shared__ char smem[];
    const uint32_t sbase = smem_u32(smem);

    const int t    = threadIdx.x;
    const int lane = t & 31;
    const int w    = t >> 5;
    const int wm   = (w & 1) * 64;
    const int wn   = (w >> 1) * 64;
    const int m0   = blockIdx.y * BM;
    const int n0   = blockIdx.x * BN;
    const int bz   = blockIdx.z;

    const __half* A = Qg + (long long)bz * NTOK * DIM;
    const __half* B = Kg + (long long)bz * NTOK * DIM;

    float acc[4][8][4];
#pragma unroll
    for (int i = 0; i < 4; i++)
#pragma unroll
        for (int j = 0; j < 8; j++)
#pragma unroll
            for (int q = 0; q < 4; q++) acc[i][j][q] = 0.0f;

    const int fr = lane >> 2;
    const int fj = lane & 3;

    MAINLOOP_BODY(A, B, DIM, DIM, DIM)

    unsigned long long L2E, MAG, NMAG, N1, C4, C3, C2, C1, C0;
    PKC(L2E, 1.4426950408889634f);
    PKC(MAG, 12582912.0f);
    PKC(NMAG, -12582912.0f);
    PKC(N1, -1.0f);
    PKC(C4, 0.0096181291f);
    PKC(C3, 0.0555041087f);
    PKC(C2, 0.2402265069f);
    PKC(C1, 0.6931471806f);
    PKC(C0, 1.0f);

    float rs[4][2];
#pragma unroll
    for (int i = 0; i < 4; i++) { rs[i][0] = 0.0f; rs[i][1] = 0.0f; }

    __half* So = Sg + (long long)bz * NTOK * NTOK;
#pragma unroll
    for (int ma = 0; ma < 4; ma++) {
        const int r0 = m0 + wm + ma * 16 + fr;
#pragma unroll
        for (int nb = 0; nb < 4; nb++) {               // na = 2*nb, 2*nb+1
            float e0 = acc[ma][2*nb][0],   e1 = acc[ma][2*nb][1];
            float e2 = acc[ma][2*nb][2],   e3 = acc[ma][2*nb][3];
            float o0 = acc[ma][2*nb+1][0], o1 = acc[ma][2*nb+1][1];
            float o2 = acc[ma][2*nb+1][2], o3 = acc[ma][2*nb+1][3];
            fexp_pk(e0, e1, L2E, MAG, NMAG, N1, C4, C3, C2, C1, C0);
            fexp_pk(e2, e3, L2E, MAG, NMAG, N1, C4, C3, C2, C1, C0);
            fexp_pk(o0, o1, L2E, MAG, NMAG, N1, C4, C3, C2, C1, C0);
            fexp_pk(o2, o3, L2E, MAG, NMAG, N1, C4, C3, C2, C1, C0);
            rs[ma][0] += (e0 + e1) + (o0 + o1);
            rs[ma][1] += (e2 + e3) + (o2 + o3);
            const long long gb = (long long)(n0 + wn + nb * 16 + 4 * fj);
            *reinterpret_cast<uint2*>(So + (long long)r0 * NTOK + gb) =
                make_uint2(h2pack(e0, e1), h2pack(o0, o1));
            *reinterpret_cast<uint2*>(So + (long long)(r0 + 8) * NTOK + gb) =
                make_uint2(h2pack(e2, e3), h2pack(o2, o3));
        }
    }

    float (*spart)[2] = reinterpret_cast<float (*)[2]>(smem + SMEM_MAIN);
    const int wgrp = w >> 1;
    __syncthreads();
#pragma unroll
    for (int ma = 0; ma < 4; ma++) {
        float s0 = rs[ma][0], s1 = rs[ma][1];
        s0 += __shfl_xor_sync(0xFFFFFFFF, s0, 1);
        s0 += __shfl_xor_sync(0xFFFFFFFF, s0, 2);
        s1 += __shfl_xor_sync(0xFFFFFFFF, s1, 1);
        s1 += __shfl_xor_sync(0xFFFFFFFF, s1, 2);
        if (fj == 0) {
            spart[wm + 16 * ma + fr][wgrp]     = s0;
            spart[wm + 16 * ma + fr + 8][wgrp] = s1;
        }
    }
    __syncthreads();
    if (t < 128) {
        const float s = spart[t][0] + spart[t][1];
        part[((long long)bz * NCOLBLK + blockIdx.x) * NTOK + m0 + t] = s;
    }
}

// ---------------- AV kernel (2 CTAs/SM): normalized fp32 out ----------------
__global__ __launch_bounds__(128, 2)
void av_h(const __half* __restrict__ Sg, const __half* __restrict__ Vtg,
          float* __restrict__ Og, const float* __restrict__ part) {
    extern __shared__ char smem[];
    const uint32_t sbase = smem_u32(smem);

    const int t    = threadIdx.x;
    const int lane = t & 31;
    const int w    = t >> 5;
    const int wm   = (w & 1) * 64;
    const int wn   = (w >> 1) * 64;
    const int m0   = blockIdx.y * BM;
    const int n0   = blockIdx.x * BN;
    const int bz   = blockIdx.z;

    const __half* A = Sg + (long long)bz * NTOK * NTOK;
    const __half* B = Vtg + (long long)bz * DIM * NTOK;

    float* invs = reinterpret_cast<float*>(smem + SMEM_MAIN);
    {
        float s = 0.0f;
        if (t < 128) {
#pragma unroll
            for (int k = 0; k < NCOLBLK; k++)
                s += part[((long long)bz * NCOLBLK + k) * NTOK + m0 + t];
            invs[t] = 1.0f / s;
        }
        __syncthreads();
    }

    float acc[4][8][4];
#pragma unroll
    for (int i = 0; i < 4; i++)
#pragma unroll
        for (int j = 0; j < 8; j++)
#pragma unroll
            for (int q = 0; q < 4; q++) acc[i][j][q] = 0.0f;

    const int fr = lane >> 2;
    const int fj = lane & 3;

    MAINLOOP_BODY(A, B, NTOK, NTOK, NTOK)

    const int fp = 2 * fj;
    float* Oo = Og + (long long)bz * NTOK * DIM;
#pragma unroll
    for (int ma = 0; ma < 4; ma++) {
        const int r0 = m0 + wm + ma * 16 + fr;
        const float i0 = invs[wm + 16 * ma + fr];
        const float i1 = invs[wm + 16 * ma + fr + 8];
#pragma unroll
        for (int na = 0; na < 8; na++) {
            const int col = n0 + wn + na * 8 + fp;
            *reinterpret_cast<float2*>(Oo + (long long)r0 * DIM + col) =
                make_float2(acc[ma][na][0] * i0, acc[ma][na][1] * i0);
            *reinterpret_cast<float2*>(Oo + (long long)(r0 + 8) * DIM + col) =
                make_float2(acc[ma][na][2] * i1, acc[ma][na][3] * i1);
        }
    }
}

// ---------------- merged input prepass (grid.y selects input) ----------------
__global__ __launch_bounds__(256)
void prep_h3(const float* __restrict__ i0, const float* __restrict__ i1,
             const float* __restrict__ i2,
             __half* __restrict__ o0, __half* __restrict__ o1,
             __half* __restrict__ o2, int n16) {
    int i = blockIdx.x * 256 + threadIdx.x;
    if (i >= n16) return;
    const float* in  = (blockIdx.y == 0) ? i0 : (blockIdx.y == 1) ? i1 : i2;
    __half*      out = (blockIdx.y == 0) ? o0 : (blockIdx.y == 1) ? o1 : o2;
    const float4* p = reinterpret_cast<const float4*>(in) + 4 * (size_t)i;
    float L[16];
    *reinterpret_cast<float4*>(L)      = p[0];
    *reinterpret_cast<float4*>(L + 4)  = p[1];
    *reinterpret_cast<float4*>(L + 8)  = p[2];
    *reinterpret_cast<float4*>(L + 12) = p[3];
    __half2 h[8];
#pragma unroll
    for (int tt = 0; tt < 4; tt++) {
        h[2 * tt]     = __floats2half2_rn(L[2 * tt],     L[2 * tt + 1]);
        h[2 * tt + 1] = __floats2half2_rn(L[2 * tt + 8], L[2 * tt + 9]);
    }
    uint4* o = reinterpret_cast<uint4*>(out + 16 * (size_t)i);
    o[0] = *reinterpret_cast<uint4*>(h);
    o[1] = *reinterpret_cast<uint4*>(h + 4);
}

// ---------------- merged weight transpose (grid.z selects weight) ----------------
__global__ void transpose512h3(const float* __restrict__ w0, const float* __restrict__ w1,
                               const float* __restrict__ w2, __half* __restrict__ out) {
    __shared__ float tile[32][33];
    const float* in = (blockIdx.z == 0) ? w0 : (blockIdx.z == 1) ? w1 : w2;
    __half* o = out + (size_t)blockIdx.z * DIM * DIM;
    int x = blockIdx.x * 32 + threadIdx.x;
    int y0 = blockIdx.y * 32;
#pragma unroll
    for (int j = threadIdx.y; j < 32; j += 8)
        tile[j][threadIdx.x] = in[(size_t)(y0 + j) * 512 + x];
    __syncthreads();
    int ox = y0 + threadIdx.x;
    int sx = (ox & ~15) | pos16(ox & 15);
    int oy0 = blockIdx.x * 32;
#pragma unroll
    for (int j = threadIdx.y; j < 32; j += 8)
        o[(size_t)(oy0 + j) * 512 + sx] = __float2half_rn(tile[threadIdx.x][j]);
}

// ---------------- launch ----------------
extern "C" void kernel_launch(void* const* d_in, const int* in_sizes, int n_in,
                              void* d_out, int out_size) {
    const float* qX  = (const float*)d_in[0];
    const float* kX  = (const float*)d_in[1];
    const float* vX  = (const float*)d_in[2];
    const float* W_Q = (const float*)d_in[3];
    const float* b_Q = (const float*)d_in[4];
    const float* W_K = (const float*)d_in[5];
    const float* b_K = (const float*)d_in[6];
    const float* W_V = (const float*)d_in[7];
    const float* b_V = (const float*)d_in[8];
    float* out = (float*)d_out;

    __half *Q, *K, *Vt, *S, *Wt;
    float* part;
    cudaGetSymbolAddress((void**)&Q,    g_Q);
    cudaGetSymbolAddress((void**)&K,    g_K);
    cudaGetSymbolAddress((void**)&Vt,   g_Vt);
    cudaGetSymbolAddress((void**)&S,    g_S);
    cudaGetSymbolAddress((void**)&Wt,   g_Wt);
    cudaGetSymbolAddress((void**)&part, g_part);

    cudaFuncSetAttribute(proj_h,   cudaFuncAttributeMaxDynamicSharedMemorySize, SMEM_TOT);
    cudaFuncSetAttribute(scores_h, cudaFuncAttributeMaxDynamicSharedMemorySize, SMEM_TOT);
    cudaFuncSetAttribute(av_h,     cudaFuncAttributeMaxDynamicSharedMemorySize, SMEM_TOT);

    const size_t nin = (size_t)MTOT * DIM;
    __half* qR = S;
    __half* kR = S + nin;
    __half* vR = S + 2 * nin;

    // 0) prepass inputs (one launch) + weights (one launch)
    {
        int n16 = (int)(nin / 16);
        dim3 pg((n16 + 255) / 256, 3, 1);
        prep_h3<<<pg, 256>>>(qX, kX, vX, qR, kR, vR, n16);
        dim3 g(16, 16, 3), b(32, 8);
        transpose512h3<<<g, b>>>(W_Q, W_K, W_V, Wt);
    }

    // 1) all three projections in one launch (z = 0:Q, 1:K, 2:V-transposed)
    {
        dim3 grid(DIM / BN, MTOT / BM, 3);
        proj_h<<<grid, 128, SMEM_TOT>>>(qR, kR, vR, Wt, b_Q, b_K, b_V, Q, K, Vt);
    }

    // 2) scores + fused exp + partial row sums
    {
        dim3 grid(NTOK / BN, NTOK / BM, NBATCH);
        scores_h<<<grid, 128, SMEM_TOT>>>(Q, K, S, part);
    }

    // 3) out = (E @ Vt^T) / rowsum
    {
        dim3 grid(DIM / BN, NTOK / BM, NBATCH);
        av_h<<<grid, 128, SMEM_TOT>>>(S, Vt, out, part);
    }
}